// round 9
// baseline (speedup 1.0000x reference)
#include <cuda_runtime.h>
#include <cuda_fp16.h>
#include <cstdint>

// Problem geometry: velocity (B=2, D=128, H=128, W=128, C=3) float32
#define B_  2
#define DIM 128
#define VOX_PER_B (DIM * DIM * DIM)          // 2097152 = 1<<21
#define N_VOX (B_ * VOX_PER_B)               // 4194304

// Ping-pong scratch: 8 B/voxel = (half2(vz,vy), half2(vx,0)) packed in uint2
__device__ uint2 g_bufA[N_VOX];
__device__ uint2 g_bufB[N_VOX];

static __device__ __forceinline__ uint2 pack_v(float vz, float vy, float vx)
{
    __half2 h0 = __floats2half2_rn(vz, vy);
    __half2 h1 = __floats2half2_rn(vx, 0.f);
    uint2 r;
    r.x = *(const unsigned int*)&h0;
    r.y = *(const unsigned int*)&h1;
    return r;
}

// -------- convert: float3 AoS fp32 input -> packed fp16, fused 1/2^STEPS scale --------
__global__ __launch_bounds__(256)
void convert_kernel(const float* __restrict__ in, uint2* __restrict__ out, float s)
{
    int t = blockIdx.x * blockDim.x + threadIdx.x;   // one thread = 4 voxels
    if (t >= N_VOX / 4) return;
    const float4* in4 = (const float4*)in;
    float4 a = in4[t * 3 + 0];
    float4 b = in4[t * 3 + 1];
    float4 c = in4[t * 3 + 2];
    out[t * 4 + 0] = pack_v(a.x * s, a.y * s, a.z * s);
    out[t * 4 + 1] = pack_v(a.w * s, b.x * s, b.y * s);
    out[t * 4 + 2] = pack_v(b.z * s, b.w * s, c.x * s);
    out[t * 4 + 3] = pack_v(c.y * s, c.z * s, c.w * s);
}

// -------- one squaring step --------
// fp16 storage, half2 gather math, own-row corner pair deduplicated via warp
// shuffle with cheap small-int row matching; skipped loads contribute w*0.
// LAST=0: dst (packed fp16 scratch). LAST=1: dst3 (stride-3 fp32 output) + identity grid.
template <int LAST>
__global__ __launch_bounds__(256)
void gridexp_step(const uint2* __restrict__ src, uint2* __restrict__ dst,
                  float* __restrict__ dst3)
{
    const int idx = blockIdx.x * 256 + threadIdx.x;   // grid sized exactly

    const int b = idx >> 21;
    const int r = idx & (VOX_PER_B - 1);
    const int z = r >> 14;
    const int y = (r >> 7) & 127;
    const int x = r & 127;
    const int lane = threadIdx.x & 31;
    const int base = b << 21;

    // own value
    uint2 pv = src[idx];
    __half2 pv0 = *(const __half2*)&pv.x;
    __half2 pv1 = *(const __half2*)&pv.y;
    float2 f0 = __half22float2(pv0);
    float vz = f0.x, vy = f0.y;
    float vx = __low2float(pv1);

    float phz = (float)z + vz;
    float phy = (float)y + vy;
    float phx = (float)x + vx;

    int iz = __float2int_rd(phz);
    int iy = __float2int_rd(phy);
    int ix = __float2int_rd(phx);
    float wz1 = phz - (float)iz;
    float wy1 = phy - (float)iy;
    float wx1 = phx - (float)ix;
    float wz0 = 1.0f - wz1, wy0 = 1.0f - wy1, wx0 = 1.0f - wx1;

    const int dz = iz - z;
    const int dy = iy - y;
    const int j0 = ix - (x - lane);                  // unwrapped corner-0 lane index
    const bool xin = (unsigned)j0 <= 30u;
    const bool valid = ((unsigned)(dz + 1) <= 1u) && ((unsigned)(dy + 1) <= 1u) && xin;
    const int rr_own = ((dz & 1) << 1) | (dy & 1);   // row index of own (z,y) when valid

    // own-row corner pair via warp shuffle
    unsigned s0x = __shfl_sync(0xffffffffu, pv.x, j0 & 31);
    unsigned s0y = __shfl_sync(0xffffffffu, pv.y, j0 & 31);
    unsigned s1x = __shfl_sync(0xffffffffu, pv.x, (j0 + 1) & 31);
    unsigned s1y = __shfl_sync(0xffffffffu, pv.y, (j0 + 1) & 31);

    int z0 = iz & 127, z1 = (iz + 1) & 127;
    int y0 = iy & 127, y1 = (iy + 1) & 127;
    int x0 = ix & 127, x1 = (ix + 1) & 127;

    int rows[4];
    rows[0] = base + (z0 << 14) + (y0 << 7);
    rows[1] = base + (z0 << 14) + (y1 << 7);
    rows[2] = base + (z1 << 14) + (y0 << 7);
    rows[3] = base + (z1 << 14) + (y1 << 7);

    __half2 wzy2[4];
    wzy2[0] = __float2half2_rn(wz0 * wy0);
    wzy2[1] = __float2half2_rn(wz0 * wy1);
    wzy2[2] = __float2half2_rn(wz1 * wy0);
    wzy2[3] = __float2half2_rn(wz1 * wy1);
    const __half2 wxlo = __float2half2_rn(wx0);
    const __half2 wxhi = __float2half2_rn(wx1);

    // own-row weight (zeroed when !valid)
    float wz_own = dz ? wz1 : wz0;
    float wy_own = dy ? wy1 : wy0;
    __half2 h2own = valid ? __float2half2_rn(wz_own * wy_own) : __float2half2_rn(0.f);

    const __half2 h2zero = __float2half2_rn(0.f);
    __half2 acc0a = h2zero, acc1a = h2zero;   // rows 0,1
    __half2 acc0b = h2zero, acc1b = h2zero;   // rows 2,3

#pragma unroll
    for (int rr = 0; rr < 4; ++rr) {
        uint2 q0 = make_uint2(0u, 0u);
        uint2 q1 = make_uint2(0u, 0u);
        const bool skip = valid && (rr_own == rr);
        if (!skip) {
            q0 = __ldg(src + rows[rr] + x0);
            q1 = __ldg(src + rows[rr] + x1);
        }
        __half2 wlo = __hmul2(wzy2[rr], wxlo);
        __half2 whi = __hmul2(wzy2[rr], wxhi);
        if (rr < 2) {
            acc0a = __hfma2(wlo, *(const __half2*)&q0.x, acc0a);
            acc1a = __hfma2(wlo, *(const __half2*)&q0.y, acc1a);
            acc0a = __hfma2(whi, *(const __half2*)&q1.x, acc0a);
            acc1a = __hfma2(whi, *(const __half2*)&q1.y, acc1a);
        } else {
            acc0b = __hfma2(wlo, *(const __half2*)&q0.x, acc0b);
            acc1b = __hfma2(wlo, *(const __half2*)&q0.y, acc1b);
            acc0b = __hfma2(whi, *(const __half2*)&q1.x, acc0b);
            acc1b = __hfma2(whi, *(const __half2*)&q1.y, acc1b);
        }
    }

    // own-row contribution from shuffled registers
    {
        __half2 wl = __hmul2(h2own, wxlo);
        __half2 wh = __hmul2(h2own, wxhi);
        acc0a = __hfma2(wl, *(const __half2*)&s0x, acc0a);
        acc1a = __hfma2(wl, *(const __half2*)&s0y, acc1a);
        acc0b = __hfma2(wh, *(const __half2*)&s1x, acc0b);
        acc1b = __hfma2(wh, *(const __half2*)&s1y, acc1b);
    }

    __half2 acc0 = __hadd2(acc0a, acc0b);
    __half2 acc1 = __hadd2(acc1a, acc1b);

    float2 s0 = __half22float2(acc0);
    float oz = vz + s0.x;
    float oy = vy + s0.y;
    float ox = vx + __low2float(acc1);

    if (LAST) {
        float* o = dst3 + (size_t)idx * 3;
        o[0] = oz + (float)z;
        o[1] = oy + (float)y;
        o[2] = ox + (float)x;
    } else {
        dst[idx] = pack_v(oz, oy, ox);
    }
}

extern "C" void kernel_launch(void* const* d_in, const int* in_sizes, int n_in,
                              void* d_out, int out_size)
{
    (void)in_sizes; (void)n_in; (void)out_size;
    const float* vel = (const float*)d_in[0];
    float* out = (float*)d_out;

    uint2* bufA = nullptr;
    uint2* bufB = nullptr;
    cudaGetSymbolAddress((void**)&bufA, g_bufA);
    cudaGetSymbolAddress((void**)&bufB, g_bufB);

    const float scale = 1.0f / 256.0f;   // 1 / 2^STEPS, STEPS = 8
    const int threads = 256;

    convert_kernel<<<(N_VOX / 4 + threads - 1) / threads, threads>>>(vel, bufA, scale);

    const int blocks = N_VOX / threads;  // exact: 16384
    uint2* cur = bufA;
    uint2* nxt = bufB;
    for (int i = 0; i < 7; ++i) {
        gridexp_step<0><<<blocks, threads>>>(cur, nxt, nullptr);
        uint2* t = cur; cur = nxt; nxt = t;
    }
    gridexp_step<1><<<blocks, threads>>>(cur, nullptr, out);
}

// round 10
// speedup vs baseline: 1.1399x; 1.1399x over previous
#include <cuda_runtime.h>
#include <cuda_fp16.h>
#include <cstdint>

// Problem geometry: velocity (B=2, D=128, H=128, W=128, C=3) float32
#define B_  2
#define DIM 128
#define VOX_PER_B (DIM * DIM * DIM)          // 2097152 = 1<<21
#define N_VOX (B_ * VOX_PER_B)               // 4194304
#define ZHALF (64 << 14)                     // offset of z+64 voxel

// Ping-pong scratch: 8 B/voxel = (half2(vz,vy), half2(vx,0)) packed in uint2
__device__ uint2 g_bufA[N_VOX];
__device__ uint2 g_bufB[N_VOX];

static __device__ __forceinline__ uint2 pack_v(float vz, float vy, float vx)
{
    __half2 h0 = __floats2half2_rn(vz, vy);
    __half2 h1 = __floats2half2_rn(vx, 0.f);
    uint2 r;
    r.x = *(const unsigned int*)&h0;
    r.y = *(const unsigned int*)&h1;
    return r;
}

// -------- convert: float3 AoS fp32 input -> packed fp16, fused 1/2^STEPS scale --------
__global__ __launch_bounds__(256)
void convert_kernel(const float* __restrict__ in, uint2* __restrict__ out, float s)
{
    int t = blockIdx.x * blockDim.x + threadIdx.x;   // one thread = 4 voxels
    if (t >= N_VOX / 4) return;
    const float4* in4 = (const float4*)in;
    float4 a = in4[t * 3 + 0];
    float4 b = in4[t * 3 + 1];
    float4 c = in4[t * 3 + 2];
    out[t * 4 + 0] = pack_v(a.x * s, a.y * s, a.z * s);
    out[t * 4 + 1] = pack_v(a.w * s, b.x * s, b.y * s);
    out[t * 4 + 2] = pack_v(b.z * s, b.w * s, c.x * s);
    out[t * 4 + 3] = pack_v(c.y * s, c.z * s, c.w * s);
}

// interpolate one voxel: fp32 own value + weights, half2 gather accumulate
static __device__ __forceinline__ void interp_one(
    const uint2* __restrict__ src, int base, int z, int y, int x,
    uint2 pv, float& oz, float& oy, float& ox)
{
    __half2 pv0 = *(const __half2*)&pv.x;
    __half2 pv1 = *(const __half2*)&pv.y;
    float2 f0 = __half22float2(pv0);
    float vz = f0.x, vy = f0.y;
    float vx = __low2float(pv1);

    float phz = (float)z + vz;
    float phy = (float)y + vy;
    float phx = (float)x + vx;

    int iz = __float2int_rd(phz);
    int iy = __float2int_rd(phy);
    int ix = __float2int_rd(phx);
    float wz1 = phz - (float)iz;
    float wy1 = phy - (float)iy;
    float wx1 = phx - (float)ix;
    float wz0 = 1.0f - wz1, wy0 = 1.0f - wy1, wx0 = 1.0f - wx1;

    int z0 = iz & 127, z1 = (iz + 1) & 127;
    int y0 = iy & 127, y1 = (iy + 1) & 127;
    int x0 = ix & 127, x1 = (ix + 1) & 127;

    int rows[4];
    rows[0] = base + (z0 << 14) + (y0 << 7);
    rows[1] = base + (z0 << 14) + (y1 << 7);
    rows[2] = base + (z1 << 14) + (y0 << 7);
    rows[3] = base + (z1 << 14) + (y1 << 7);

    // issue all 8 loads up front for max MLP
    uint2 q[8];
#pragma unroll
    for (int rr = 0; rr < 4; ++rr) {
        q[2 * rr + 0] = __ldg(src + rows[rr] + x0);
        q[2 * rr + 1] = __ldg(src + rows[rr] + x1);
    }

    __half2 wzy2[4];
    wzy2[0] = __float2half2_rn(wz0 * wy0);
    wzy2[1] = __float2half2_rn(wz0 * wy1);
    wzy2[2] = __float2half2_rn(wz1 * wy0);
    wzy2[3] = __float2half2_rn(wz1 * wy1);
    const __half2 wxlo = __float2half2_rn(wx0);
    const __half2 wxhi = __float2half2_rn(wx1);

    const __half2 h2zero = __float2half2_rn(0.f);
    __half2 acc0a = h2zero, acc1a = h2zero;
    __half2 acc0b = h2zero, acc1b = h2zero;
#pragma unroll
    for (int rr = 0; rr < 2; ++rr) {
        __half2 wlo = __hmul2(wzy2[rr], wxlo);
        __half2 whi = __hmul2(wzy2[rr], wxhi);
        acc0a = __hfma2(wlo, *(const __half2*)&q[2 * rr].x, acc0a);
        acc1a = __hfma2(wlo, *(const __half2*)&q[2 * rr].y, acc1a);
        acc0a = __hfma2(whi, *(const __half2*)&q[2 * rr + 1].x, acc0a);
        acc1a = __hfma2(whi, *(const __half2*)&q[2 * rr + 1].y, acc1a);
    }
#pragma unroll
    for (int rr = 2; rr < 4; ++rr) {
        __half2 wlo = __hmul2(wzy2[rr], wxlo);
        __half2 whi = __hmul2(wzy2[rr], wxhi);
        acc0b = __hfma2(wlo, *(const __half2*)&q[2 * rr].x, acc0b);
        acc1b = __hfma2(wlo, *(const __half2*)&q[2 * rr].y, acc1b);
        acc0b = __hfma2(whi, *(const __half2*)&q[2 * rr + 1].x, acc0b);
        acc1b = __hfma2(whi, *(const __half2*)&q[2 * rr + 1].y, acc1b);
    }
    __half2 acc0 = __hadd2(acc0a, acc0b);
    __half2 acc1 = __hadd2(acc1a, acc1b);

    float2 s0 = __half22float2(acc0);
    oz = vz + s0.x;
    oy = vy + s0.y;
    ox = vx + __low2float(acc1);
}

// -------- one squaring step: 2 voxels per thread, split across z (z and z+64) --------
// Same y,x per pair -> each gather LDG keeps the 32-consecutive-x footprint of the
// 1-voxel kernel, but per-thread MLP doubles.
// LAST=0: dst (packed fp16 scratch). LAST=1: dst3 (stride-3 fp32 output) + identity grid.
template <int LAST>
__global__ __launch_bounds__(256)
void gridexp_step(const uint2* __restrict__ src, uint2* __restrict__ dst,
                  float* __restrict__ dst3)
{
    const int t = blockIdx.x * 256 + threadIdx.x;     // 0 .. N_VOX/2-1
    const int b = t >> 20;
    const int r = t & ((1 << 20) - 1);                // voxel within lower z-half
    const int z = r >> 14;                            // 0..63
    const int y = (r >> 7) & 127;
    const int x = r & 127;
    const int base = b << 21;
    const int idx0 = base + r;
    const int idx1 = idx0 + ZHALF;

    uint2 pv0 = __ldg(src + idx0);
    uint2 pv1 = __ldg(src + idx1);

    float oz0, oy0, ox0, oz1, oy1, ox1;
    interp_one(src, base, z,      y, x, pv0, oz0, oy0, ox0);
    interp_one(src, base, z + 64, y, x, pv1, oz1, oy1, ox1);

    if (LAST) {
        float* o0 = dst3 + (size_t)idx0 * 3;
        o0[0] = oz0 + (float)z;
        o0[1] = oy0 + (float)y;
        o0[2] = ox0 + (float)x;
        float* o1 = dst3 + (size_t)idx1 * 3;
        o1[0] = oz1 + (float)(z + 64);
        o1[1] = oy1 + (float)y;
        o1[2] = ox1 + (float)x;
    } else {
        dst[idx0] = pack_v(oz0, oy0, ox0);
        dst[idx1] = pack_v(oz1, oy1, ox1);
    }
}

extern "C" void kernel_launch(void* const* d_in, const int* in_sizes, int n_in,
                              void* d_out, int out_size)
{
    (void)in_sizes; (void)n_in; (void)out_size;
    const float* vel = (const float*)d_in[0];
    float* out = (float*)d_out;

    uint2* bufA = nullptr;
    uint2* bufB = nullptr;
    cudaGetSymbolAddress((void**)&bufA, g_bufA);
    cudaGetSymbolAddress((void**)&bufB, g_bufB);

    const float scale = 1.0f / 256.0f;   // 1 / 2^STEPS, STEPS = 8
    const int threads = 256;

    convert_kernel<<<(N_VOX / 4 + threads - 1) / threads, threads>>>(vel, bufA, scale);

    const int blocks = (N_VOX / 2) / threads;  // exact: 8192
    uint2* cur = bufA;
    uint2* nxt = bufB;
    for (int i = 0; i < 7; ++i) {
        gridexp_step<0><<<blocks, threads>>>(cur, nxt, nullptr);
        uint2* t = cur; cur = nxt; nxt = t;
    }
    gridexp_step<1><<<blocks, threads>>>(cur, nullptr, out);
}